// round 5
// baseline (speedup 1.0000x reference)
#include <cuda_runtime.h>
#include <cuda_bf16.h>
#include <cuda_fp16.h>
#include <mma.h>
#include <cstdint>

using namespace nvcuda;

#define NN 50000
#define EE 800000
#define DD 128
#define EPSI 0.001f
#define NCH 36                     // K = 2304 = 36 * 64 (18 per weight set)
#define MT 64                      // M tile rows per CTA
#define LDAE 72                    // A tile ld (bf16), 144 B
#define LDBE 136                   // B tile ld (bf16), 272 B
#define A_TILE (MT * LDAE * 2)     // 9216 B
#define B_TILE (64 * LDBE * 2)     // 17408 B
#define KAN_SMEM (2 * (A_TILE + B_TILE))  // 53248 B (epilogue reuses as 64x132 f32)

// ---------------- device scratch ----------------------------------------------
__device__ float g_x[(size_t)NN * DD];
__device__ __half2 g_xh[(size_t)NN * 64];
__device__ __half2 g_aggh[2][(size_t)NN * 64];
__device__ float g_dis[NN];
__device__ float g_deg[NN];
__device__ __nv_bfloat16 g_wt[2 * 1152 * DD];  // [set][k][o], k-major (chunks 0..35)
__device__ int g_is64;

// ---------------- helpers ------------------------------------------------------
__device__ __forceinline__ uint32_t smem_u32(const void* p) {
    uint32_t a;
    asm("{ .reg .u64 t; cvta.to.shared.u64 t, %1; cvt.u32.u64 %0, t; }" : "=r"(a) : "l"(p));
    return a;
}
__device__ __forceinline__ void cp_async16(uint32_t dst, const void* src) {
    asm volatile("cp.async.cg.shared.global [%0], [%1], 16;" :: "r"(dst), "l"(src));
}
__device__ __forceinline__ void cp_commit() { asm volatile("cp.async.commit_group;"); }
__device__ __forceinline__ void cp_wait0() { asm volatile("cp.async.wait_group 0;"); }
__device__ __forceinline__ unsigned pack2(float a, float b) {
    __nv_bfloat162 h = __floats2bfloat162_rn(a, b);
    return *(unsigned*)&h;
}
__device__ __forceinline__ int get_idx(const void* p, long long e) {
    if (g_is64) return (int)((const long long*)p)[e];
    return ((const int*)p)[e];
}

// ---------------- local cubic B-spline: 4 nonzero bases -> 4 packed u32 -------
__device__ __forceinline__ void bs8_fast(float x, uint32_t* w) {
    float T = fmaf(x, 2.5f, 5.5f);
    T = fminf(fmaxf(T, 2.0f), 8.999f);
    float jf = floorf(T);
    float u = T - jf;
    int s = (int)jf - 3;
    float u2 = u * u, u3 = u2 * u;
    float v0 = fmaf(u, -0.5f, 1.0f / 6.0f);
    v0 = fmaf(u2, 0.5f, v0);
    v0 = fmaf(u3, -1.0f / 6.0f, v0);
    float v1 = fmaf(u2, -1.0f, 2.0f / 3.0f);
    v1 = fmaf(u3, 0.5f, v1);
    float v2 = fmaf(u, 0.5f, 1.0f / 6.0f);
    v2 = fmaf(u2, 0.5f, v2);
    v2 = fmaf(u3, -0.5f, v2);
    float v3 = u3 * (1.0f / 6.0f);
    uint32_t p01 = pack2(v0, v1), p23 = pack2(v2, v3);
    int sh = (s & 1) << 4;
    int p = s >> 1;
    uint32_t r0 = p01 << sh;
    uint32_t r1 = __funnelshift_l(p01, p23, sh);
    uint32_t r2 = sh ? (p23 >> 16) : 0u;
#pragma unroll
    for (int i = 0; i < 4; i++) {
        int d = i - p;
        w[i] = (d == 0) ? r0 : (d == 1) ? r1 : (d == 2) ? r2 : 0u;
    }
}

// ---------------- precompute kernels -------------------------------------------
__global__ void detect_kernel(const int* ei) {
    int is64 = 1;
    for (int k = 0; k < 16; k++)
        if (ei[2 * k + 1] != 0) { is64 = 0; break; }
    g_is64 = is64;
}

#define N_XH ((long long)NN * 32)
#define N_CLR ((long long)2 * NN * 16)
#define N_W ((long long)2 * 1152 * 128)
#define N_SETUP (N_XH + N_CLR + N_W + NN)

__global__ void setup_kernel(const float* __restrict__ x,
                             const float* __restrict__ bwl, const float* __restrict__ swl,
                             const float* __restrict__ bwc, const float* __restrict__ swc) {
    long long idx = (long long)blockIdx.x * 256 + threadIdx.x;
    if (idx < N_XH) {
        float4 v = ((const float4*)x)[idx];
        __half2 h0 = __floats2half2_rn(v.x, v.y);
        __half2 h1 = __floats2half2_rn(v.z, v.w);
        ((uint2*)g_xh)[idx] = make_uint2(*(uint32_t*)&h0, *(uint32_t*)&h1);
    } else if (idx < N_XH + N_CLR) {
        ((uint4*)g_aggh)[idx - N_XH] = make_uint4(0, 0, 0, 0);
    } else if (idx < N_XH + N_CLR + N_W) {
        long long r = idx - N_XH - N_CLR;
        int set = (int)(r / (1152 * 128));
        int q = (int)(r - (long long)set * (1152 * 128));
        int k = q >> 7, o = q & 127;
        const float* bw = set ? bwc : bwl;
        const float* sw = set ? swc : swl;
        float v = (k < DD) ? bw[o * DD + k] : sw[(long long)o * 1024 + (k - DD)];
        g_wt[r] = __float2bfloat16(v);
    } else if (idx < N_SETUP) {
        g_deg[idx - N_XH - N_CLR - N_W] = 0.0f;
    }
}

__global__ void deg_kernel(const void* __restrict__ ei) {
    int e = blockIdx.x * blockDim.x + threadIdx.x;
    if (e < EE) atomicAdd(&g_deg[get_idx(ei, (long long)EE + e)], 1.0f);
}
__global__ void dis_kernel() {
    int v = blockIdx.x * blockDim.x + threadIdx.x;
    if (v < NN) g_dis[v] = rsqrtf(g_deg[v] + 1.0f);
}

// ---------------- fused dual-branch KAN kernel (M tile = 64) -------------------
// out = xin + EPSI * ( featL(hin)@WL + featC(agg)@WC )
// Chunks 0..17 from hin (fp32), 18..35 from agg (fp16); per set: 2 silu + 16 spline.
template <int WH>
__global__ __launch_bounds__(256, 3) void kan_fused(const float* __restrict__ hin,
                                                    const __half2* __restrict__ agg,
                                                    const float* __restrict__ xin,
                                                    float* __restrict__ out,
                                                    __half2* __restrict__ outh) {
    extern __shared__ char sm[];
    uint32_t smb = smem_u32(sm);
    int tid = threadIdx.x;
    int row0 = blockIdx.x * MT;

    int m = tid >> 2, q = tid & 3;           // 64 rows x 4 quarter-threads
    bool valid = (row0 + m) < NN;
    const float* xrow = hin + (size_t)(row0 + m) * DD;
    const __half2* arow = agg + (size_t)(row0 + m) * 64;

    uint32_t aoff[2] = {0u, (uint32_t)A_TILE};
    uint32_t boff[2] = {(uint32_t)(2 * A_TILE), (uint32_t)(2 * A_TILE + B_TILE)};
    uint32_t fbase = (uint32_t)(m * (LDAE * 2) + q * 32);

    uint32_t fr[8];                          // 16 bf16 = this thread's k-slice
    auto gen = [&](int c) {
        int set = (c >= 18);
        int cs = set ? c - 18 : c;
        if (cs < 2) {                        // silu chunk: 16 values
            float v[16];
            if (!set) {
#pragma unroll
                for (int g = 0; g < 4; g++) {
                    float4 t = make_float4(0.f, 0.f, 0.f, 0.f);
                    if (valid) t = *(const float4*)(xrow + cs * 64 + q * 16 + g * 4);
                    v[g * 4 + 0] = t.x; v[g * 4 + 1] = t.y;
                    v[g * 4 + 2] = t.z; v[g * 4 + 3] = t.w;
                }
            } else {
#pragma unroll
                for (int g = 0; g < 2; g++) {
                    uint4 u = make_uint4(0, 0, 0, 0);
                    if (valid) u = *(const uint4*)(arow + cs * 32 + q * 8 + g * 4);
                    float2 f0 = __half22float2(*(__half2*)&u.x);
                    float2 f1 = __half22float2(*(__half2*)&u.y);
                    float2 f2 = __half22float2(*(__half2*)&u.z);
                    float2 f3 = __half22float2(*(__half2*)&u.w);
                    v[g * 8 + 0] = f0.x; v[g * 8 + 1] = f0.y;
                    v[g * 8 + 2] = f1.x; v[g * 8 + 3] = f1.y;
                    v[g * 8 + 4] = f2.x; v[g * 8 + 5] = f2.y;
                    v[g * 8 + 6] = f3.x; v[g * 8 + 7] = f3.y;
                }
            }
#pragma unroll
            for (int i = 0; i < 16; i += 2) {
                float a = v[i] / (1.0f + __expf(-v[i]));
                float b = v[i + 1] / (1.0f + __expf(-v[i + 1]));
                fr[i >> 1] = pack2(a, b);
            }
        } else {                             // spline chunk: 2 dims x 8 bases
            float x0 = 0.f, x1 = 0.f;
            if (!set) {
                if (valid) {
                    float2 xv = *(const float2*)(xrow + (cs - 2) * 8 + q * 2);
                    x0 = xv.x; x1 = xv.y;
                }
            } else {
                if (valid) {
                    __half2 u = arow[(cs - 2) * 4 + q];
                    float2 f = __half22float2(u);
                    x0 = f.x; x1 = f.y;
                }
            }
            bs8_fast(x0, fr);
            bs8_fast(x1, fr + 4);
        }
    };
    auto sts = [&](int buf) {
        uint32_t base = smb + aoff[buf] + fbase;
        asm volatile("st.shared.v4.b32 [%0], {%1,%2,%3,%4};"
                     :: "r"(base), "r"(fr[0]), "r"(fr[1]), "r"(fr[2]), "r"(fr[3]));
        asm volatile("st.shared.v4.b32 [%0], {%1,%2,%3,%4};"
                     :: "r"(base + 16), "r"(fr[4]), "r"(fr[5]), "r"(fr[6]), "r"(fr[7]));
    };
    auto ldb = [&](int buf, int c) {
        const char* src = (const char*)(g_wt) + (size_t)c * 64 * DD * 2;
#pragma unroll
        for (int qq = 0; qq < 4; qq++) {
            int i = tid + qq * 256;
            int r = i >> 4, c16 = i & 15;
            cp_async16(smb + boff[buf] + r * (LDBE * 2) + c16 * 16, src + i * 16);
        }
        cp_commit();
    };

    int warp = tid >> 5;
    int m0 = (warp & 1) * 32, n0 = (warp >> 1) * 32;   // 2 x 4 warp grid, 32x32 tiles
    wmma::fragment<wmma::accumulator, 16, 16, 16, float> acc[2][2];
#pragma unroll
    for (int i = 0; i < 2; i++)
#pragma unroll
        for (int j = 0; j < 2; j++) wmma::fill_fragment(acc[i][j], 0.0f);

    gen(0); sts(0); ldb(0, 0);

    for (int c = 0; c < NCH; c++) {
        int cb = c & 1, nb = cb ^ 1;
        if (c + 1 < NCH) gen(c + 1);
        cp_wait0();
        __syncthreads();
        if (c + 1 < NCH) { sts(nb); ldb(nb, c + 1); }

        const __nv_bfloat16* As = (const __nv_bfloat16*)(sm + aoff[cb]);
        const __nv_bfloat16* Bs = (const __nv_bfloat16*)(sm + boff[cb]);
#pragma unroll
        for (int kk = 0; kk < 4; kk++) {
            wmma::fragment<wmma::matrix_a, 16, 16, 16, __nv_bfloat16, wmma::row_major> a0, a1;
            wmma::load_matrix_sync(a0, As + m0 * LDAE + kk * 16, LDAE);
            wmma::load_matrix_sync(a1, As + (m0 + 16) * LDAE + kk * 16, LDAE);
#pragma unroll
            for (int j = 0; j < 2; j++) {
                wmma::fragment<wmma::matrix_b, 16, 16, 16, __nv_bfloat16, wmma::row_major> bf;
                wmma::load_matrix_sync(bf, Bs + kk * 16 * LDBE + n0 + j * 16, LDBE);
                wmma::mma_sync(acc[0][j], a0, bf, acc[0][j]);
                wmma::mma_sync(acc[1][j], a1, bf, acc[1][j]);
            }
        }
    }

    // epilogue: stage f32 tile (64 x 132), fused Euler update + half mirror
    __syncthreads();
    float* cs = (float*)sm;
#pragma unroll
    for (int i = 0; i < 2; i++)
#pragma unroll
        for (int j = 0; j < 2; j++)
            wmma::store_matrix_sync(cs + (m0 + i * 16) * 132 + n0 + j * 16, acc[i][j],
                                    132, wmma::mem_row_major);
    __syncthreads();

    if (valid) {
        const float* crow = cs + m * 132 + q * 32;
        float4* po = (float4*)(out + (size_t)(row0 + m) * DD + q * 32);
        const float4* xr = (const float4*)(xin + (size_t)(row0 + m) * DD + q * 32);
        uint2* ph = (uint2*)(outh + (size_t)(row0 + m) * 64 + q * 16);
#pragma unroll
        for (int g = 0; g < 8; g++) {
            float4 a = *(const float4*)(crow + g * 4);
            float4 x4 = xr[g];
            float4 o = make_float4(x4.x + EPSI * a.x, x4.y + EPSI * a.y,
                                   x4.z + EPSI * a.z, x4.w + EPSI * a.w);
            po[g] = o;
            if (WH) {
                __half2 h0 = __floats2half2_rn(o.x, o.y);
                __half2 h1 = __floats2half2_rn(o.z, o.w);
                ph[g] = make_uint2(*(uint32_t*)&h0, *(uint32_t*)&h1);
            }
        }
    }
}

// ---------------- half scatter: agg[dst] += dis[src]*dis[dst] * h[src] ---------
__global__ void scatter_half(const uint4* __restrict__ hh, const void* __restrict__ ei,
                             __half2* __restrict__ agg) {
    long long gid = (long long)blockIdx.x * blockDim.x + threadIdx.x;
    long long e = gid >> 4;
    int lane = (int)(gid & 15);
    if (e >= EE) return;
    int src = get_idx(ei, e);
    int dst = get_idx(ei, (long long)EE + e);
    __half2 nh = __float2half2_rn(g_dis[src] * g_dis[dst]);
    uint4 v = hh[(size_t)src * 16 + lane];
    __half2 a0 = __hmul2(*(__half2*)&v.x, nh);
    __half2 a1 = __hmul2(*(__half2*)&v.y, nh);
    __half2 a2 = __hmul2(*(__half2*)&v.z, nh);
    __half2 a3 = __hmul2(*(__half2*)&v.w, nh);
    __half2* p = agg + (size_t)dst * 64 + lane * 4;
    asm volatile("red.global.add.noftz.v4.f16x2 [%0], {%1,%2,%3,%4};"
                 :: "l"(p), "r"(*(uint32_t*)&a0), "r"(*(uint32_t*)&a1),
                    "r"(*(uint32_t*)&a2), "r"(*(uint32_t*)&a3) : "memory");
}

// ---------------- launch -------------------------------------------------------
extern "C" void kernel_launch(void* const* d_in, const int* in_sizes, int n_in,
                              void* d_out, int out_size) {
    const float* x = (const float*)d_in[0];
    const void* ei = d_in[1];
    const float* bwl = (const float*)d_in[2];
    const float* swl = (const float*)d_in[3];
    const float* bwc = (const float*)d_in[4];
    const float* swc = (const float*)d_in[5];
    float* out = (float*)d_out;

    cudaFuncSetAttribute(kan_fused<0>, cudaFuncAttributeMaxDynamicSharedMemorySize, KAN_SMEM);
    cudaFuncSetAttribute(kan_fused<1>, cudaFuncAttributeMaxDynamicSharedMemorySize, KAN_SMEM);

    void *xp, *xhp, *aggp;
    cudaGetSymbolAddress(&xp, g_x);
    cudaGetSymbolAddress(&xhp, g_xh);
    cudaGetSymbolAddress(&aggp, g_aggh);
    float* gx = (float*)xp;
    __half2* gxh = (__half2*)xhp;
    __half2* agg0 = (__half2*)aggp;
    __half2* agg1 = agg0 + (size_t)NN * 64;

    const int GRID_KAN = (NN + MT - 1) / MT;   // 782

    // 1: detect   2: setup   3: deg   4: dis   5: scatter0   6: kan0 (ncu capture)
    detect_kernel<<<1, 1>>>((const int*)ei);
    setup_kernel<<<(int)((N_SETUP + 255) / 256), 256>>>(x, bwl, swl, bwc, swc);
    deg_kernel<<<(EE + 255) / 256, 256>>>(ei);
    dis_kernel<<<(NN + 255) / 256, 256>>>();

    scatter_half<<<(int)((EE * 16LL + 255) / 256), 256>>>((const uint4*)gxh, ei, agg0);
    kan_fused<1><<<GRID_KAN, 256, KAN_SMEM>>>(x, agg0, x, gx, gxh);

    scatter_half<<<(int)((EE * 16LL + 255) / 256), 256>>>((const uint4*)gxh, ei, agg1);
    kan_fused<0><<<GRID_KAN, 256, KAN_SMEM>>>(gx, agg1, gx, out, gxh);
}

// round 6
// speedup vs baseline: 1.8342x; 1.8342x over previous
#include <cuda_runtime.h>
#include <cuda_fp16.h>
#include <mma.h>
#include <cstdint>

using namespace nvcuda;

#define NN 50000
#define EE 800000
#define DD 128
#define EPSI 0.001f
#define NCH 36                     // K = 2304 = 36 * 64 (18 per weight set)
#define MT 128                     // M tile rows per CTA
#define NTHR 512
#define LDAE 72                    // A tile ld (halfs), 144 B
#define LDBE 136                   // B tile ld (halfs), 272 B
#define LDCE 136                   // epilogue staging ld (halfs)
#define A_TILE (MT * LDAE * 2)     // 18432 B
#define B_TILE (64 * LDBE * 2)     // 17408 B
#define KAN_SMEM (2 * (A_TILE + B_TILE))  // 71680 B (epilogue: 128 x 136 half)

// ---------------- device scratch ----------------------------------------------
__device__ float g_x[(size_t)NN * DD];
__device__ __half2 g_xh[(size_t)NN * 64];
__device__ __half2 g_aggh[2][(size_t)NN * 64];
__device__ float g_deg[NN];
__device__ __half g_wt[2 * 1152 * DD];  // [set][k][o], k-major (36 chunks of 64 k)
__device__ int g_is64;

// ---------------- helpers ------------------------------------------------------
__device__ __forceinline__ uint32_t smem_u32(const void* p) {
    uint32_t a;
    asm("{ .reg .u64 t; cvta.to.shared.u64 t, %1; cvt.u32.u64 %0, t; }" : "=r"(a) : "l"(p));
    return a;
}
__device__ __forceinline__ void cp_async16(uint32_t dst, const void* src) {
    asm volatile("cp.async.cg.shared.global [%0], [%1], 16;" :: "r"(dst), "l"(src));
}
__device__ __forceinline__ void cp_commit() { asm volatile("cp.async.commit_group;"); }
__device__ __forceinline__ void cp_wait0() { asm volatile("cp.async.wait_group 0;"); }
__device__ __forceinline__ unsigned pack2h(float a, float b) {
    __half2 h = __floats2half2_rn(a, b);
    return *(unsigned*)&h;
}
__device__ __forceinline__ int get_idx(const void* p, long long e) {
    if (g_is64) return (int)((const long long*)p)[e];
    return ((const int*)p)[e];
}

// ---------------- local cubic B-spline: 4 nonzero bases -> 4 packed u32 -------
__device__ __forceinline__ void bs8_fast(float x, uint32_t* w) {
    float T = fmaf(x, 2.5f, 5.5f);
    T = fminf(fmaxf(T, 2.0f), 8.999f);
    float jf = floorf(T);
    float u = T - jf;
    int s = (int)jf - 3;
    float u2 = u * u, u3 = u2 * u;
    float v0 = fmaf(u, -0.5f, 1.0f / 6.0f);
    v0 = fmaf(u2, 0.5f, v0);
    v0 = fmaf(u3, -1.0f / 6.0f, v0);
    float v1 = fmaf(u2, -1.0f, 2.0f / 3.0f);
    v1 = fmaf(u3, 0.5f, v1);
    float v2 = fmaf(u, 0.5f, 1.0f / 6.0f);
    v2 = fmaf(u2, 0.5f, v2);
    v2 = fmaf(u3, -0.5f, v2);
    float v3 = u3 * (1.0f / 6.0f);
    uint32_t p01 = pack2h(v0, v1), p23 = pack2h(v2, v3);
    int sh = (s & 1) << 4;
    int p = s >> 1;
    uint32_t r0 = p01 << sh;
    uint32_t r1 = __funnelshift_l(p01, p23, sh);
    uint32_t r2 = sh ? (p23 >> 16) : 0u;
#pragma unroll
    for (int i = 0; i < 4; i++) {
        int d = i - p;
        w[i] = (d == 0) ? r0 : (d == 1) ? r1 : (d == 2) ? r2 : 0u;
    }
}

// ---------------- setup: x->half, clear agg/deg, weights->half, detect ---------
#define N_XH ((long long)NN * 32)
#define N_CLR ((long long)2 * NN * 16)
#define N_W ((long long)2 * 1152 * 128)
#define N_SETUP (N_XH + N_CLR + N_W + NN + 1)

__global__ void setup_kernel(const float* __restrict__ x,
                             const float* __restrict__ bwl, const float* __restrict__ swl,
                             const float* __restrict__ bwc, const float* __restrict__ swc,
                             const int* __restrict__ ei) {
    long long idx = (long long)blockIdx.x * 256 + threadIdx.x;
    if (idx < N_XH) {
        float4 v = ((const float4*)x)[idx];
        __half2 h0 = __floats2half2_rn(v.x, v.y);
        __half2 h1 = __floats2half2_rn(v.z, v.w);
        ((uint2*)g_xh)[idx] = make_uint2(*(uint32_t*)&h0, *(uint32_t*)&h1);
    } else if (idx < N_XH + N_CLR) {
        ((uint4*)g_aggh)[idx - N_XH] = make_uint4(0, 0, 0, 0);
    } else if (idx < N_XH + N_CLR + N_W) {
        long long r = idx - N_XH - N_CLR;
        int set = (int)(r / (1152 * 128));
        int q = (int)(r - (long long)set * (1152 * 128));
        int k = q >> 7, o = q & 127;
        const float* bw = set ? bwc : bwl;
        const float* sw = set ? swc : swl;
        float v = (k < DD) ? bw[o * DD + k] : sw[(long long)o * 1024 + (k - DD)];
        g_wt[r] = __float2half(v);
    } else if (idx < N_XH + N_CLR + N_W + NN) {
        g_deg[idx - N_XH - N_CLR - N_W] = 0.0f;
    } else if (idx == N_XH + N_CLR + N_W + NN) {
        int is64 = 1;
        for (int k = 0; k < 16; k++)
            if (ei[2 * k + 1] != 0) { is64 = 0; break; }
        g_is64 = is64;
    }
}

__global__ void deg_kernel(const void* __restrict__ ei) {
    int e = blockIdx.x * blockDim.x + threadIdx.x;
    if (e < EE) atomicAdd(&g_deg[get_idx(ei, (long long)EE + e)], 1.0f);
}

// ---------------- fused dual-branch KAN kernel (MT=128, 512 thr, fp16 acc) -----
// out = xin + EPSI * ( featL(hin)@WL + featC(agg)@WC )
// Chunks 0..17 from hin (fp32), 18..35 from agg (fp16); per set: 2 silu + 16 spline.
template <int WH>
__global__ __launch_bounds__(NTHR, 2) void kan_fused(const float* __restrict__ hin,
                                                     const __half2* __restrict__ agg,
                                                     const float* __restrict__ xin,
                                                     float* __restrict__ out,
                                                     __half2* __restrict__ outh) {
    extern __shared__ char sm[];
    uint32_t smb = smem_u32(sm);
    int tid = threadIdx.x;
    int row0 = blockIdx.x * MT;

    int m = tid >> 2, q = tid & 3;           // 128 rows x 4 quarter-threads
    bool valid = (row0 + m) < NN;
    const float* xrow = hin + (size_t)(row0 + m) * DD;
    const __half2* arow = agg + (size_t)(row0 + m) * 64;

    uint32_t aoff[2] = {0u, (uint32_t)A_TILE};
    uint32_t boff[2] = {(uint32_t)(2 * A_TILE), (uint32_t)(2 * A_TILE + B_TILE)};
    uint32_t fbase = (uint32_t)(m * (LDAE * 2) + q * 32);

    uint32_t fr[8];                          // 16 half = this thread's k-slice
    auto gen = [&](int c) {
        int set = (c >= 18);
        int cs = set ? c - 18 : c;
        if (cs < 2) {                        // silu chunk: 16 values
            float v[16];
            if (!set) {
#pragma unroll
                for (int g = 0; g < 4; g++) {
                    float4 t = make_float4(0.f, 0.f, 0.f, 0.f);
                    if (valid) t = *(const float4*)(xrow + cs * 64 + q * 16 + g * 4);
                    v[g * 4 + 0] = t.x; v[g * 4 + 1] = t.y;
                    v[g * 4 + 2] = t.z; v[g * 4 + 3] = t.w;
                }
            } else {
#pragma unroll
                for (int g = 0; g < 2; g++) {
                    uint4 u = make_uint4(0, 0, 0, 0);
                    if (valid) u = *(const uint4*)(arow + cs * 32 + q * 8 + g * 4);
                    float2 f0 = __half22float2(*(__half2*)&u.x);
                    float2 f1 = __half22float2(*(__half2*)&u.y);
                    float2 f2 = __half22float2(*(__half2*)&u.z);
                    float2 f3 = __half22float2(*(__half2*)&u.w);
                    v[g * 8 + 0] = f0.x; v[g * 8 + 1] = f0.y;
                    v[g * 8 + 2] = f1.x; v[g * 8 + 3] = f1.y;
                    v[g * 8 + 4] = f2.x; v[g * 8 + 5] = f2.y;
                    v[g * 8 + 6] = f3.x; v[g * 8 + 7] = f3.y;
                }
            }
#pragma unroll
            for (int i = 0; i < 16; i += 2) {
                float a = v[i] / (1.0f + __expf(-v[i]));
                float b = v[i + 1] / (1.0f + __expf(-v[i + 1]));
                fr[i >> 1] = pack2h(a, b);
            }
        } else {                             // spline chunk: 2 dims x 8 bases
            float x0 = 0.f, x1 = 0.f;
            if (!set) {
                if (valid) {
                    float2 xv = *(const float2*)(xrow + (cs - 2) * 8 + q * 2);
                    x0 = xv.x; x1 = xv.y;
                }
            } else {
                if (valid) {
                    __half2 u = arow[(cs - 2) * 4 + q];
                    float2 f = __half22float2(u);
                    x0 = f.x; x1 = f.y;
                }
            }
            bs8_fast(x0, fr);
            bs8_fast(x1, fr + 4);
        }
    };
    auto sts = [&](int buf) {
        uint32_t base = smb + aoff[buf] + fbase;
        asm volatile("st.shared.v4.b32 [%0], {%1,%2,%3,%4};"
                     :: "r"(base), "r"(fr[0]), "r"(fr[1]), "r"(fr[2]), "r"(fr[3]));
        asm volatile("st.shared.v4.b32 [%0], {%1,%2,%3,%4};"
                     :: "r"(base + 16), "r"(fr[4]), "r"(fr[5]), "r"(fr[6]), "r"(fr[7]));
    };
    auto ldb = [&](int buf, int c) {
        const char* src = (const char*)(g_wt) + (size_t)c * 64 * DD * 2;
#pragma unroll
        for (int qq = 0; qq < 2; qq++) {
            int i = tid + qq * NTHR;
            int r = i >> 4, c16 = i & 15;
            cp_async16(smb + boff[buf] + r * (LDBE * 2) + c16 * 16, src + i * 16);
        }
        cp_commit();
    };

    int warp = tid >> 5;
    int m0 = (warp & 3) * 32, n0 = (warp >> 2) * 32;   // 4x4 warp grid, 32x32 tiles
    wmma::fragment<wmma::accumulator, 16, 16, 16, __half> acc[2][2];
#pragma unroll
    for (int i = 0; i < 2; i++)
#pragma unroll
        for (int j = 0; j < 2; j++) wmma::fill_fragment(acc[i][j], __float2half(0.0f));

    gen(0); sts(0); ldb(0, 0);

    for (int c = 0; c < NCH; c++) {
        int cb = c & 1, nb = cb ^ 1;
        if (c + 1 < NCH) gen(c + 1);
        cp_wait0();
        __syncthreads();
        if (c + 1 < NCH) { sts(nb); ldb(nb, c + 1); }

        const __half* As = (const __half*)(sm + aoff[cb]);
        const __half* Bs = (const __half*)(sm + boff[cb]);
#pragma unroll
        for (int kk = 0; kk < 4; kk++) {
            wmma::fragment<wmma::matrix_a, 16, 16, 16, __half, wmma::row_major> a0, a1;
            wmma::load_matrix_sync(a0, As + m0 * LDAE + kk * 16, LDAE);
            wmma::load_matrix_sync(a1, As + (m0 + 16) * LDAE + kk * 16, LDAE);
#pragma unroll
            for (int j = 0; j < 2; j++) {
                wmma::fragment<wmma::matrix_b, 16, 16, 16, __half, wmma::row_major> bf;
                wmma::load_matrix_sync(bf, Bs + kk * 16 * LDBE + n0 + j * 16, LDBE);
                wmma::mma_sync(acc[0][j], a0, bf, acc[0][j]);
                wmma::mma_sync(acc[1][j], a1, bf, acc[1][j]);
            }
        }
    }

    // epilogue: stage half tile (128 x LDCE), fused Euler update + half mirror
    __syncthreads();
    __half* cs = (__half*)sm;
#pragma unroll
    for (int i = 0; i < 2; i++)
#pragma unroll
        for (int j = 0; j < 2; j++)
            wmma::store_matrix_sync(cs + (m0 + i * 16) * LDCE + n0 + j * 16, acc[i][j],
                                    LDCE, wmma::mem_row_major);
    __syncthreads();

    if (valid) {
        const __half2* crow = (const __half2*)(cs + m * LDCE + q * 32);
        float4* po = (float4*)(out + (size_t)(row0 + m) * DD + q * 32);
        const float4* xr = (const float4*)(xin + (size_t)(row0 + m) * DD + q * 32);
        uint2* ph = (uint2*)(outh + (size_t)(row0 + m) * 64 + q * 16);
#pragma unroll
        for (int g = 0; g < 8; g++) {
            float2 a0 = __half22float2(crow[g * 2]);
            float2 a1 = __half22float2(crow[g * 2 + 1]);
            float4 x4 = xr[g];
            float4 o = make_float4(x4.x + EPSI * a0.x, x4.y + EPSI * a0.y,
                                   x4.z + EPSI * a1.x, x4.w + EPSI * a1.y);
            po[g] = o;
            if (WH) {
                __half2 h0 = __floats2half2_rn(o.x, o.y);
                __half2 h1 = __floats2half2_rn(o.z, o.w);
                ph[g] = make_uint2(*(uint32_t*)&h0, *(uint32_t*)&h1);
            }
        }
    }
}

// ---------------- half scatter: agg[dst] += rsqrt(ds+1)rsqrt(dd+1) * h[src] ----
__global__ void scatter_half(const uint4* __restrict__ hh, const void* __restrict__ ei,
                             __half2* __restrict__ agg) {
    long long gid = (long long)blockIdx.x * blockDim.x + threadIdx.x;
    long long e = gid >> 4;
    int lane = (int)(gid & 15);
    if (e >= EE) return;
    int src = get_idx(ei, e);
    int dst = get_idx(ei, (long long)EE + e);
    float nrm = rsqrtf(g_deg[src] + 1.0f) * rsqrtf(g_deg[dst] + 1.0f);
    __half2 nh = __float2half2_rn(nrm);
    uint4 v = hh[(size_t)src * 16 + lane];
    __half2 a0 = __hmul2(*(__half2*)&v.x, nh);
    __half2 a1 = __hmul2(*(__half2*)&v.y, nh);
    __half2 a2 = __hmul2(*(__half2*)&v.z, nh);
    __half2 a3 = __hmul2(*(__half2*)&v.w, nh);
    __half2* p = agg + (size_t)dst * 64 + lane * 4;
    asm volatile("red.global.add.noftz.v4.f16x2 [%0], {%1,%2,%3,%4};"
                 :: "l"(p), "r"(*(uint32_t*)&a0), "r"(*(uint32_t*)&a1),
                    "r"(*(uint32_t*)&a2), "r"(*(uint32_t*)&a3) : "memory");
}

// ---------------- launch -------------------------------------------------------
extern "C" void kernel_launch(void* const* d_in, const int* in_sizes, int n_in,
                              void* d_out, int out_size) {
    const float* x = (const float*)d_in[0];
    const void* ei = d_in[1];
    const float* bwl = (const float*)d_in[2];
    const float* swl = (const float*)d_in[3];
    const float* bwc = (const float*)d_in[4];
    const float* swc = (const float*)d_in[5];
    float* out = (float*)d_out;

    cudaFuncSetAttribute(kan_fused<0>, cudaFuncAttributeMaxDynamicSharedMemorySize, KAN_SMEM);
    cudaFuncSetAttribute(kan_fused<1>, cudaFuncAttributeMaxDynamicSharedMemorySize, KAN_SMEM);

    void *xp, *xhp, *aggp;
    cudaGetSymbolAddress(&xp, g_x);
    cudaGetSymbolAddress(&xhp, g_xh);
    cudaGetSymbolAddress(&aggp, g_aggh);
    float* gx = (float*)xp;
    __half2* gxh = (__half2*)xhp;
    __half2* agg0 = (__half2*)aggp;
    __half2* agg1 = agg0 + (size_t)NN * 64;

    const int GRID_KAN = (NN + MT - 1) / MT;   // 391

    // launches: 1 setup  2 deg  3 scatter0  4 kan0 (ncu capture)  5 scatter1  6 kan1
    setup_kernel<<<(int)((N_SETUP + 255) / 256), 256>>>(x, bwl, swl, bwc, swc, (const int*)ei);
    deg_kernel<<<(EE + 255) / 256, 256>>>(ei);

    scatter_half<<<(int)((EE * 16LL + 255) / 256), 256>>>((const uint4*)gxh, ei, agg0);
    kan_fused<1><<<GRID_KAN, NTHR, KAN_SMEM>>>(x, agg0, x, gx, gxh);

    scatter_half<<<(int)((EE * 16LL + 255) / 256), 256>>>((const uint4*)gxh, ei, agg1);
    kan_fused<0><<<GRID_KAN, NTHR, KAN_SMEM>>>(gx, agg1, gx, out, gxh);
}

// round 7
// speedup vs baseline: 1.9226x; 1.0482x over previous
#include <cuda_runtime.h>
#include <cuda_fp16.h>
#include <mma.h>
#include <cstdint>

using namespace nvcuda;

#define NN 50000
#define EE 800000
#define DD 128
#define EPSI 0.001f
#define NCH 36                     // K = 2304 = 36 * 64 (18 per weight set)
#define MT 128                     // M tile rows per CTA
#define NTHR 512
#define LDAE 72                    // A tile ld (halfs), 144 B
#define LDBE 136                   // B tile ld (halfs), 272 B
#define LDCE 136                   // epilogue staging ld (halfs)
#define A_TILE (MT * LDAE * 2)     // 18432 B
#define B_TILE (64 * LDBE * 2)     // 17408 B
#define KAN_SMEM (2 * (A_TILE + B_TILE))  // 71680 B (epilogue: 128 x 136 half)

// ---------------- device scratch ----------------------------------------------
__device__ float g_x[(size_t)NN * DD];
__device__ __half2 g_xh[(size_t)NN * 64];
__device__ __half2 g_aggh[2][(size_t)NN * 64];
__device__ float g_deg[NN];
__device__ __half g_wt[2 * 1152 * DD];  // [set][k][o], k-major (36 chunks of 64 k)
__device__ int g_is64;

// ---------------- helpers ------------------------------------------------------
__device__ __forceinline__ uint32_t smem_u32(const void* p) {
    uint32_t a;
    asm("{ .reg .u64 t; cvta.to.shared.u64 t, %1; cvt.u32.u64 %0, t; }" : "=r"(a) : "l"(p));
    return a;
}
__device__ __forceinline__ void cp_async16(uint32_t dst, const void* src) {
    asm volatile("cp.async.cg.shared.global [%0], [%1], 16;" :: "r"(dst), "l"(src));
}
__device__ __forceinline__ void cp_commit() { asm volatile("cp.async.commit_group;"); }
__device__ __forceinline__ void cp_wait0() { asm volatile("cp.async.wait_group 0;"); }
__device__ __forceinline__ unsigned pack2h(float a, float b) {
    __half2 h = __floats2half2_rn(a, b);
    return *(unsigned*)&h;
}
__device__ __forceinline__ int get_idx(const void* p, long long e) {
    if (g_is64) return (int)((const long long*)p)[e];
    return ((const int*)p)[e];
}

// ---------------- local cubic B-spline: 4 nonzero bases -> 4 packed u32 -------
__device__ __forceinline__ void bs8_fast(float x, uint32_t* w) {
    float T = fmaf(x, 2.5f, 5.5f);
    T = fminf(fmaxf(T, 2.0f), 8.999f);
    float jf = floorf(T);
    float u = T - jf;
    int s = (int)jf - 3;
    float u2 = u * u, u3 = u2 * u;
    float v0 = fmaf(u, -0.5f, 1.0f / 6.0f);
    v0 = fmaf(u2, 0.5f, v0);
    v0 = fmaf(u3, -1.0f / 6.0f, v0);
    float v1 = fmaf(u2, -1.0f, 2.0f / 3.0f);
    v1 = fmaf(u3, 0.5f, v1);
    float v2 = fmaf(u, 0.5f, 1.0f / 6.0f);
    v2 = fmaf(u2, 0.5f, v2);
    v2 = fmaf(u3, -0.5f, v2);
    float v3 = u3 * (1.0f / 6.0f);
    uint32_t p01 = pack2h(v0, v1), p23 = pack2h(v2, v3);
    int sh = (s & 1) << 4;
    int p = s >> 1;
    uint32_t r0 = p01 << sh;
    uint32_t r1 = __funnelshift_l(p01, p23, sh);
    uint32_t r2 = sh ? (p23 >> 16) : 0u;
#pragma unroll
    for (int i = 0; i < 4; i++) {
        int d = i - p;
        w[i] = (d == 0) ? r0 : (d == 1) ? r1 : (d == 2) ? r2 : 0u;
    }
}

// ---------------- setup: x->half, clear agg/deg, weights->half, detect ---------
#define N_XH ((long long)NN * 32)
#define N_CLR ((long long)2 * NN * 16)
#define N_W ((long long)2 * 1152 * 128)
#define N_SETUP (N_XH + N_CLR + N_W + NN + 1)

__global__ void setup_kernel(const float* __restrict__ x,
                             const float* __restrict__ bwl, const float* __restrict__ swl,
                             const float* __restrict__ bwc, const float* __restrict__ swc,
                             const int* __restrict__ ei) {
    long long idx = (long long)blockIdx.x * 256 + threadIdx.x;
    if (idx < N_XH) {
        float4 v = ((const float4*)x)[idx];
        __half2 h0 = __floats2half2_rn(v.x, v.y);
        __half2 h1 = __floats2half2_rn(v.z, v.w);
        ((uint2*)g_xh)[idx] = make_uint2(*(uint32_t*)&h0, *(uint32_t*)&h1);
    } else if (idx < N_XH + N_CLR) {
        ((uint4*)g_aggh)[idx - N_XH] = make_uint4(0, 0, 0, 0);
    } else if (idx < N_XH + N_CLR + N_W) {
        long long r = idx - N_XH - N_CLR;
        int set = (int)(r / (1152 * 128));
        int q = (int)(r - (long long)set * (1152 * 128));
        int k = q >> 7, o = q & 127;
        const float* bw = set ? bwc : bwl;
        const float* sw = set ? swc : swl;
        float v = (k < DD) ? bw[o * DD + k] : sw[(long long)o * 1024 + (k - DD)];
        g_wt[r] = __float2half(v);
    } else if (idx < N_XH + N_CLR + N_W + NN) {
        g_deg[idx - N_XH - N_CLR - N_W] = 0.0f;
    } else if (idx == N_XH + N_CLR + N_W + NN) {
        int is64 = 1;
        for (int k = 0; k < 16; k++)
            if (ei[2 * k + 1] != 0) { is64 = 0; break; }
        g_is64 = is64;
    }
}

__global__ void deg_kernel(const void* __restrict__ ei) {
    int e = blockIdx.x * blockDim.x + threadIdx.x;
    if (e < EE) atomicAdd(&g_deg[get_idx(ei, (long long)EE + e)], 1.0f);
}

// ---------------- fused dual-branch KAN kernel (MT=128, 512 thr, fp16 acc) -----
// out = xin + EPSI * ( featL(xh)@WL + featC(agg)@WC )
// Features for BOTH branches read from fp16 mirrors (single code path).
// Chunks 0..17: from hh; 18..35: from agg. Per set: 2 silu + 16 spline chunks.
template <int WH>
__global__ __launch_bounds__(NTHR, 2) void kan_fused(const __half2* __restrict__ hh,
                                                     const __half2* __restrict__ agg,
                                                     const float* __restrict__ xin,
                                                     float* __restrict__ out,
                                                     __half2* __restrict__ outh) {
    extern __shared__ char sm[];
    uint32_t smb = smem_u32(sm);
    int tid = threadIdx.x;
    int row0 = blockIdx.x * MT;

    int m = tid >> 2, q = tid & 3;             // 128 rows x 4 quarter-threads
    bool valid = (row0 + m) < NN;
    int rowc = min(row0 + m, NN - 1);          // clamp: loads always in-bounds
    const __half2* hrow = hh + (size_t)rowc * 64;
    const __half2* arow = agg + (size_t)rowc * 64;

    uint32_t aoff[2] = {0u, (uint32_t)A_TILE};
    uint32_t boff[2] = {(uint32_t)(2 * A_TILE), (uint32_t)(2 * A_TILE + B_TILE)};
    uint32_t fbase = (uint32_t)(m * (LDAE * 2) + q * 32);

    uint32_t fr[8];                            // 16 half = this thread's k-slice
    auto gen = [&](int c) {
        const __half2* r = (c < 18) ? hrow : arow;
        int cs = (c < 18) ? c : c - 18;
        if (cs < 2) {                          // silu chunk: 16 values
#pragma unroll
            for (int g = 0; g < 2; g++) {
                uint4 u = *(const uint4*)(r + cs * 32 + q * 8 + g * 4);
                float2 f0 = __half22float2(*(__half2*)&u.x);
                float2 f1 = __half22float2(*(__half2*)&u.y);
                float2 f2 = __half22float2(*(__half2*)&u.z);
                float2 f3 = __half22float2(*(__half2*)&u.w);
                float v[8] = {f0.x, f0.y, f1.x, f1.y, f2.x, f2.y, f3.x, f3.y};
#pragma unroll
                for (int i = 0; i < 8; i += 2) {
                    float a = __fdividef(v[i], 1.0f + __expf(-v[i]));
                    float b = __fdividef(v[i + 1], 1.0f + __expf(-v[i + 1]));
                    fr[g * 4 + (i >> 1)] = pack2h(a, b);
                }
            }
        } else {                               // spline chunk: 2 dims x 8 bases
            float2 f = __half22float2(r[(cs - 2) * 4 + q]);
            bs8_fast(f.x, fr);
            bs8_fast(f.y, fr + 4);
        }
    };
    auto sts = [&](int buf) {
        uint32_t base = smb + aoff[buf] + fbase;
        asm volatile("st.shared.v4.b32 [%0], {%1,%2,%3,%4};"
                     :: "r"(base), "r"(fr[0]), "r"(fr[1]), "r"(fr[2]), "r"(fr[3]));
        asm volatile("st.shared.v4.b32 [%0], {%1,%2,%3,%4};"
                     :: "r"(base + 16), "r"(fr[4]), "r"(fr[5]), "r"(fr[6]), "r"(fr[7]));
    };
    auto ldb = [&](int buf, int c) {
        const char* src = (const char*)(g_wt) + (size_t)c * 64 * DD * 2;
#pragma unroll
        for (int qq = 0; qq < 2; qq++) {
            int i = tid + qq * NTHR;
            int r = i >> 4, c16 = i & 15;
            cp_async16(smb + boff[buf] + r * (LDBE * 2) + c16 * 16, src + i * 16);
        }
        cp_commit();
    };

    int warp = tid >> 5;
    int m0 = (warp & 3) * 32, n0 = (warp >> 2) * 32;   // 4x4 warp grid, 32x32 tiles
    wmma::fragment<wmma::accumulator, 16, 16, 16, __half> acc[2][2];
#pragma unroll
    for (int i = 0; i < 2; i++)
#pragma unroll
        for (int j = 0; j < 2; j++) wmma::fill_fragment(acc[i][j], __float2half(0.0f));

    gen(0); sts(0); ldb(0, 0);

    for (int c = 0; c < NCH; c++) {
        int cb = c & 1, nb = cb ^ 1;
        if (c + 1 < NCH) gen(c + 1);
        cp_wait0();
        __syncthreads();
        if (c + 1 < NCH) { sts(nb); ldb(nb, c + 1); }

        const __half* As = (const __half*)(sm + aoff[cb]);
        const __half* Bs = (const __half*)(sm + boff[cb]);
#pragma unroll
        for (int kk = 0; kk < 4; kk++) {
            wmma::fragment<wmma::matrix_a, 16, 16, 16, __half, wmma::row_major> a0, a1;
            wmma::load_matrix_sync(a0, As + m0 * LDAE + kk * 16, LDAE);
            wmma::load_matrix_sync(a1, As + (m0 + 16) * LDAE + kk * 16, LDAE);
#pragma unroll
            for (int j = 0; j < 2; j++) {
                wmma::fragment<wmma::matrix_b, 16, 16, 16, __half, wmma::row_major> bf;
                wmma::load_matrix_sync(bf, Bs + kk * 16 * LDBE + n0 + j * 16, LDBE);
                wmma::mma_sync(acc[0][j], a0, bf, acc[0][j]);
                wmma::mma_sync(acc[1][j], a1, bf, acc[1][j]);
            }
        }
    }

    // epilogue: stage half tile (128 x LDCE), fused Euler update + half mirror
    __syncthreads();
    __half* cs = (__half*)sm;
#pragma unroll
    for (int i = 0; i < 2; i++)
#pragma unroll
        for (int j = 0; j < 2; j++)
            wmma::store_matrix_sync(cs + (m0 + i * 16) * LDCE + n0 + j * 16, acc[i][j],
                                    LDCE, wmma::mem_row_major);
    __syncthreads();

    if (valid) {
        const __half2* crow = (const __half2*)(cs + m * LDCE + q * 32);
        float4* po = (float4*)(out + (size_t)(row0 + m) * DD + q * 32);
        const float4* xr = (const float4*)(xin + (size_t)(row0 + m) * DD + q * 32);
        uint2* ph = (uint2*)(outh + (size_t)(row0 + m) * 64 + q * 16);
#pragma unroll
        for (int g = 0; g < 8; g++) {
            float2 a0 = __half22float2(crow[g * 2]);
            float2 a1 = __half22float2(crow[g * 2 + 1]);
            float4 x4 = xr[g];
            float4 o = make_float4(x4.x + EPSI * a0.x, x4.y + EPSI * a0.y,
                                   x4.z + EPSI * a1.x, x4.w + EPSI * a1.y);
            po[g] = o;
            if (WH) {
                __half2 h0 = __floats2half2_rn(o.x, o.y);
                __half2 h1 = __floats2half2_rn(o.z, o.w);
                ph[g] = make_uint2(*(uint32_t*)&h0, *(uint32_t*)&h1);
            }
        }
    }
}

// ---------------- half scatter: agg[dst] += rsqrt(ds+1)rsqrt(dd+1) * h[src] ----
__global__ void scatter_half(const uint4* __restrict__ hh, const void* __restrict__ ei,
                             __half2* __restrict__ agg) {
    long long gid = (long long)blockIdx.x * blockDim.x + threadIdx.x;
    long long e = gid >> 4;
    int lane = (int)(gid & 15);
    if (e >= EE) return;
    int src = get_idx(ei, e);
    int dst = get_idx(ei, (long long)EE + e);
    float nrm = rsqrtf(g_deg[src] + 1.0f) * rsqrtf(g_deg[dst] + 1.0f);
    __half2 nh = __float2half2_rn(nrm);
    uint4 v = hh[(size_t)src * 16 + lane];
    __half2 a0 = __hmul2(*(__half2*)&v.x, nh);
    __half2 a1 = __hmul2(*(__half2*)&v.y, nh);
    __half2 a2 = __hmul2(*(__half2*)&v.z, nh);
    __half2 a3 = __hmul2(*(__half2*)&v.w, nh);
    __half2* p = agg + (size_t)dst * 64 + lane * 4;
    asm volatile("red.global.add.noftz.v4.f16x2 [%0], {%1,%2,%3,%4};"
                 :: "l"(p), "r"(*(uint32_t*)&a0), "r"(*(uint32_t*)&a1),
                    "r"(*(uint32_t*)&a2), "r"(*(uint32_t*)&a3) : "memory");
}

// ---------------- launch -------------------------------------------------------
extern "C" void kernel_launch(void* const* d_in, const int* in_sizes, int n_in,
                              void* d_out, int out_size) {
    const float* x = (const float*)d_in[0];
    const void* ei = d_in[1];
    const float* bwl = (const float*)d_in[2];
    const float* swl = (const float*)d_in[3];
    const float* bwc = (const float*)d_in[4];
    const float* swc = (const float*)d_in[5];
    float* out = (float*)d_out;

    cudaFuncSetAttribute(kan_fused<0>, cudaFuncAttributeMaxDynamicSharedMemorySize, KAN_SMEM);
    cudaFuncSetAttribute(kan_fused<1>, cudaFuncAttributeMaxDynamicSharedMemorySize, KAN_SMEM);

    void *xp, *xhp, *aggp;
    cudaGetSymbolAddress(&xp, g_x);
    cudaGetSymbolAddress(&xhp, g_xh);
    cudaGetSymbolAddress(&aggp, g_aggh);
    float* gx = (float*)xp;
    __half2* gxh = (__half2*)xhp;
    __half2* agg0 = (__half2*)aggp;
    __half2* agg1 = agg0 + (size_t)NN * 64;

    const int GRID_KAN = (NN + MT - 1) / MT;   // 391

    // launches: 1 setup  2 deg  3 scatter0  4 kan0 (ncu capture)  5 scatter1  6 kan1
    setup_kernel<<<(int)((N_SETUP + 255) / 256), 256>>>(x, bwl, swl, bwc, swc, (const int*)ei);
    deg_kernel<<<(EE + 255) / 256, 256>>>(ei);

    scatter_half<<<(int)((EE * 16LL + 255) / 256), 256>>>((const uint4*)gxh, ei, agg0);
    kan_fused<1><<<GRID_KAN, NTHR, KAN_SMEM>>>(gxh, agg0, x, gx, gxh);

    scatter_half<<<(int)((EE * 16LL + 255) / 256), 256>>>((const uint4*)gxh, ei, agg1);
    kan_fused<0><<<GRID_KAN, NTHR, KAN_SMEM>>>(gxh, agg1, gx, out, gxh);
}

// round 8
// speedup vs baseline: 2.1081x; 1.0965x over previous
#include <cuda_runtime.h>
#include <cuda_fp16.h>
#include <mma.h>
#include <cstdint>

using namespace nvcuda;

#define NN 50000
#define EE 800000
#define DD 128
#define EPSI 0.001f
#define NCH 36                     // K = 2304 = 36 * 64 (18 per weight set)
#define MT 128                     // M tile rows per CTA
#define NTHR 512
#define LDAE 72                    // A tile ld (halfs), 144 B
#define LDBE 136                   // B tile ld (halfs), 272 B
#define LDCE 136                   // epilogue staging ld (halfs)
#define A_TILE (MT * LDAE * 2)     // 18432 B
#define B_TILE (64 * LDBE * 2)     // 17408 B
#define KAN_SMEM (2 * (A_TILE + B_TILE))  // 71680 B (epilogue: 128 x 136 half)

// ---------------- device scratch ----------------------------------------------
__device__ float g_x[(size_t)NN * DD];
__device__ __half2 g_xh[(size_t)NN * 64];
__device__ __half2 g_aggh[2][(size_t)NN * 64];
__device__ float g_deg[NN];
__device__ __half g_wt[2 * 1152 * DD];  // [set][k][o], k-major (36 chunks of 64 k)
__device__ int g_is64;

// ---------------- helpers ------------------------------------------------------
__device__ __forceinline__ uint32_t smem_u32(const void* p) {
    uint32_t a;
    asm("{ .reg .u64 t; cvta.to.shared.u64 t, %1; cvt.u32.u64 %0, t; }" : "=r"(a) : "l"(p));
    return a;
}
__device__ __forceinline__ void cp_async16(uint32_t dst, const void* src) {
    asm volatile("cp.async.cg.shared.global [%0], [%1], 16;" :: "r"(dst), "l"(src));
}
__device__ __forceinline__ void cp_commit() { asm volatile("cp.async.commit_group;"); }
__device__ __forceinline__ void cp_wait0() { asm volatile("cp.async.wait_group 0;"); }
__device__ __forceinline__ unsigned pack2h(float a, float b) {
    __half2 h = __floats2half2_rn(a, b);
    return *(unsigned*)&h;
}
__device__ __forceinline__ int get_idx(const void* p, long long e) {
    if (g_is64) return (int)((const long long*)p)[e];
    return ((const int*)p)[e];
}

// ---------------- local cubic B-spline: 4 nonzero bases -> 4 packed u32 -------
__device__ __forceinline__ void bs8_fast(float x, uint32_t* w) {
    float T = fmaf(x, 2.5f, 5.5f);
    T = fminf(fmaxf(T, 2.0f), 8.999f);
    float jf = floorf(T);
    float u = T - jf;
    int s = (int)jf - 3;
    float u2 = u * u, u3 = u2 * u;
    float v0 = fmaf(u, -0.5f, 1.0f / 6.0f);
    v0 = fmaf(u2, 0.5f, v0);
    v0 = fmaf(u3, -1.0f / 6.0f, v0);
    float v1 = fmaf(u2, -1.0f, 2.0f / 3.0f);
    v1 = fmaf(u3, 0.5f, v1);
    float v2 = fmaf(u, 0.5f, 1.0f / 6.0f);
    v2 = fmaf(u2, 0.5f, v2);
    v2 = fmaf(u3, -0.5f, v2);
    float v3 = u3 * (1.0f / 6.0f);
    uint32_t p01 = pack2h(v0, v1), p23 = pack2h(v2, v3);
    int sh = (s & 1) << 4;
    int p = s >> 1;
    uint32_t r0 = p01 << sh;
    uint32_t r1 = __funnelshift_l(p01, p23, sh);
    uint32_t r2 = sh ? (p23 >> 16) : 0u;
#pragma unroll
    for (int i = 0; i < 4; i++) {
        int d = i - p;
        w[i] = (d == 0) ? r0 : (d == 1) ? r1 : (d == 2) ? r2 : 0u;
    }
}

// ---------------- setup: x->half, clear agg/deg, weights->half, detect ---------
#define N_XH ((long long)NN * 32)
#define N_CLR ((long long)2 * NN * 16)
#define N_W ((long long)2 * 1152 * 128)
#define N_SETUP (N_XH + N_CLR + N_W + NN + 1)

__global__ void setup_kernel(const float* __restrict__ x,
                             const float* __restrict__ bwl, const float* __restrict__ swl,
                             const float* __restrict__ bwc, const float* __restrict__ swc,
                             const int* __restrict__ ei) {
    long long idx = (long long)blockIdx.x * 256 + threadIdx.x;
    if (idx < N_XH) {
        float4 v = ((const float4*)x)[idx];
        __half2 h0 = __floats2half2_rn(v.x, v.y);
        __half2 h1 = __floats2half2_rn(v.z, v.w);
        ((uint2*)g_xh)[idx] = make_uint2(*(uint32_t*)&h0, *(uint32_t*)&h1);
    } else if (idx < N_XH + N_CLR) {
        ((uint4*)g_aggh)[idx - N_XH] = make_uint4(0, 0, 0, 0);
    } else if (idx < N_XH + N_CLR + N_W) {
        long long r = idx - N_XH - N_CLR;
        int set = (int)(r / (1152 * 128));
        int q = (int)(r - (long long)set * (1152 * 128));
        int k = q >> 7, o = q & 127;
        const float* bw = set ? bwc : bwl;
        const float* sw = set ? swc : swl;
        float v = (k < DD) ? bw[o * DD + k] : sw[(long long)o * 1024 + (k - DD)];
        g_wt[r] = __float2half(v);
    } else if (idx < N_XH + N_CLR + N_W + NN) {
        g_deg[idx - N_XH - N_CLR - N_W] = 0.0f;
    } else if (idx == N_XH + N_CLR + N_W + NN) {
        int is64 = 1;
        for (int k = 0; k < 16; k++)
            if (ei[2 * k + 1] != 0) { is64 = 0; break; }
        g_is64 = is64;
    }
}

__global__ void deg_kernel(const void* __restrict__ ei) {
    int e = blockIdx.x * blockDim.x + threadIdx.x;
    if (e < EE) atomicAdd(&g_deg[get_idx(ei, (long long)EE + e)], 1.0f);
}

// ---------------- fused dual-branch KAN kernel (MT=128, 512 thr, fp16 acc) -----
// out = xin + EPSI * ( featL(xh)@WL + featC(agg)@WC )
// Fully-unrolled chunk loop: all branches/addresses resolve at compile time.
template <int WH>
__global__ __launch_bounds__(NTHR, 2) void kan_fused(const __half2* __restrict__ hh,
                                                     const __half2* __restrict__ agg,
                                                     const float* __restrict__ xin,
                                                     float* __restrict__ out,
                                                     __half2* __restrict__ outh) {
    extern __shared__ char sm[];
    uint32_t smb = smem_u32(sm);
    int tid = threadIdx.x;
    int row0 = blockIdx.x * MT;

    int m = tid >> 2, q = tid & 3;             // 128 rows x 4 quarter-threads
    bool valid = (row0 + m) < NN;
    int rowc = min(row0 + m, NN - 1);          // clamp: loads always in-bounds
    const __half2* hrow = hh + (size_t)rowc * 64;
    const __half2* arow = agg + (size_t)rowc * 64;

    const uint32_t aoff[2] = {0u, (uint32_t)A_TILE};
    const uint32_t boff[2] = {(uint32_t)(2 * A_TILE), (uint32_t)(2 * A_TILE + B_TILE)};
    uint32_t fbase = (uint32_t)(m * (LDAE * 2) + q * 32);

    uint32_t fr[8];                            // 16 half = this thread's k-slice
    const __half2 H2_ONE = __floats2half2_rn(1.0f, 1.0f);
    const __half2 H2_NL2E = __floats2half2_rn(-1.4426950408889634f, -1.4426950408889634f);

    auto gen = [&](int c) {                    // c is compile-time after unroll
        const __half2* r = (c < 18) ? hrow : arow;
        int cs = (c < 18) ? c : c - 18;
        if (cs < 2) {                          // silu chunk: 16 values, pure half2
#pragma unroll
            for (int g = 0; g < 2; g++) {
                uint4 u = *(const uint4*)(r + cs * 32 + q * 8 + g * 4);
                uint32_t uw[4] = {u.x, u.y, u.z, u.w};
#pragma unroll
                for (int i = 0; i < 4; i++) {
                    __half2 h = *(__half2*)&uw[i];
                    __half2 e = h2exp2(__hmul2(h, H2_NL2E));       // exp(-h)
                    __half2 s = __hmul2(h, h2rcp(__hadd2(H2_ONE, e)));
                    fr[g * 4 + i] = *(uint32_t*)&s;
                }
            }
        } else {                               // spline chunk: 2 dims x 8 bases
            float2 f = __half22float2(r[(cs - 2) * 4 + q]);
            bs8_fast(f.x, fr);
            bs8_fast(f.y, fr + 4);
        }
    };
    auto sts = [&](int buf) {
        uint32_t base = smb + aoff[buf] + fbase;
        asm volatile("st.shared.v4.b32 [%0], {%1,%2,%3,%4};"
                     :: "r"(base), "r"(fr[0]), "r"(fr[1]), "r"(fr[2]), "r"(fr[3]));
        asm volatile("st.shared.v4.b32 [%0], {%1,%2,%3,%4};"
                     :: "r"(base + 16), "r"(fr[4]), "r"(fr[5]), "r"(fr[6]), "r"(fr[7]));
    };
    auto ldb = [&](int buf, int c) {
        const char* src = (const char*)(g_wt) + (size_t)c * 64 * DD * 2;
#pragma unroll
        for (int qq = 0; qq < 2; qq++) {
            int i = tid + qq * NTHR;
            int r = i >> 4, c16 = i & 15;
            cp_async16(smb + boff[buf] + r * (LDBE * 2) + c16 * 16, src + i * 16);
        }
        cp_commit();
    };

    int warp = tid >> 5;
    int m0 = (warp & 3) * 32, n0 = (warp >> 2) * 32;   // 4x4 warp grid, 32x32 tiles
    wmma::fragment<wmma::accumulator, 16, 16, 16, __half> acc[2][2];
#pragma unroll
    for (int i = 0; i < 2; i++)
#pragma unroll
        for (int j = 0; j < 2; j++) wmma::fill_fragment(acc[i][j], __float2half(0.0f));

    gen(0); sts(0); ldb(0, 0);

#pragma unroll
    for (int c = 0; c < NCH; c++) {            // FULL unroll: c compile-time
        const int cb = c & 1, nb = cb ^ 1;
        if (c + 1 < NCH) gen(c + 1);
        cp_wait0();
        __syncthreads();
        if (c + 1 < NCH) { sts(nb); ldb(nb, c + 1); }

        const __half* As = (const __half*)(sm + aoff[cb]);
        const __half* Bs = (const __half*)(sm + boff[cb]);
#pragma unroll
        for (int kk = 0; kk < 4; kk++) {
            wmma::fragment<wmma::matrix_a, 16, 16, 16, __half, wmma::row_major> a0, a1;
            wmma::load_matrix_sync(a0, As + m0 * LDAE + kk * 16, LDAE);
            wmma::load_matrix_sync(a1, As + (m0 + 16) * LDAE + kk * 16, LDAE);
#pragma unroll
            for (int j = 0; j < 2; j++) {
                wmma::fragment<wmma::matrix_b, 16, 16, 16, __half, wmma::row_major> bf;
                wmma::load_matrix_sync(bf, Bs + kk * 16 * LDBE + n0 + j * 16, LDBE);
                wmma::mma_sync(acc[0][j], a0, bf, acc[0][j]);
                wmma::mma_sync(acc[1][j], a1, bf, acc[1][j]);
            }
        }
    }

    // epilogue: stage half tile (128 x LDCE), fused Euler update + half mirror
    __syncthreads();
    __half* cs = (__half*)sm;
#pragma unroll
    for (int i = 0; i < 2; i++)
#pragma unroll
        for (int j = 0; j < 2; j++)
            wmma::store_matrix_sync(cs + (m0 + i * 16) * LDCE + n0 + j * 16, acc[i][j],
                                    LDCE, wmma::mem_row_major);
    __syncthreads();

    if (valid) {
        const __half2* crow = (const __half2*)(cs + m * LDCE + q * 32);
        float4* po = (float4*)(out + (size_t)(row0 + m) * DD + q * 32);
        const float4* xr = (const float4*)(xin + (size_t)(row0 + m) * DD + q * 32);
        uint2* ph = (uint2*)(outh + (size_t)(row0 + m) * 64 + q * 16);
#pragma unroll
        for (int g = 0; g < 8; g++) {
            float2 a0 = __half22float2(crow[g * 2]);
            float2 a1 = __half22float2(crow[g * 2 + 1]);
            float4 x4 = xr[g];
            float4 o = make_float4(x4.x + EPSI * a0.x, x4.y + EPSI * a0.y,
                                   x4.z + EPSI * a1.x, x4.w + EPSI * a1.y);
            po[g] = o;
            if (WH) {
                __half2 h0 = __floats2half2_rn(o.x, o.y);
                __half2 h1 = __floats2half2_rn(o.z, o.w);
                ph[g] = make_uint2(*(uint32_t*)&h0, *(uint32_t*)&h1);
            }
        }
    }
}

// ---------------- half scatter: agg[dst] += rsqrt(ds+1)rsqrt(dd+1) * h[src] ----
__global__ void scatter_half(const uint4* __restrict__ hh, const void* __restrict__ ei,
                             __half2* __restrict__ agg) {
    long long gid = (long long)blockIdx.x * blockDim.x + threadIdx.x;
    long long e = gid >> 4;
    int lane = (int)(gid & 15);
    if (e >= EE) return;
    int src = get_idx(ei, e);
    int dst = get_idx(ei, (long long)EE + e);
    float nrm = rsqrtf(g_deg[src] + 1.0f) * rsqrtf(g_deg[dst] + 1.0f);
    __half2 nh = __float2half2_rn(nrm);
    uint4 v = hh[(size_t)src * 16 + lane];
    __half2 a0 = __hmul2(*(__half2*)&v.x, nh);
    __half2 a1 = __hmul2(*(__half2*)&v.y, nh);
    __half2 a2 = __hmul2(*(__half2*)&v.z, nh);
    __half2 a3 = __hmul2(*(__half2*)&v.w, nh);
    __half2* p = agg + (size_t)dst * 64 + lane * 4;
    asm volatile("red.global.add.noftz.v4.f16x2 [%0], {%1,%2,%3,%4};"
                 :: "l"(p), "r"(*(uint32_t*)&a0), "r"(*(uint32_t*)&a1),
                    "r"(*(uint32_t*)&a2), "r"(*(uint32_t*)&a3) : "memory");
}

// ---------------- launch -------------------------------------------------------
extern "C" void kernel_launch(void* const* d_in, const int* in_sizes, int n_in,
                              void* d_out, int out_size) {
    const float* x = (const float*)d_in[0];
    const void* ei = d_in[1];
    const float* bwl = (const float*)d_in[2];
    const float* swl = (const float*)d_in[3];
    const float* bwc = (const float*)d_in[4];
    const float* swc = (const float*)d_in[5];
    float* out = (float*)d_out;

    cudaFuncSetAttribute(kan_fused<0>, cudaFuncAttributeMaxDynamicSharedMemorySize, KAN_SMEM);
    cudaFuncSetAttribute(kan_fused<1>, cudaFuncAttributeMaxDynamicSharedMemorySize, KAN_SMEM);

    void *xp, *xhp, *aggp;
    cudaGetSymbolAddress(&xp, g_x);
    cudaGetSymbolAddress(&xhp, g_xh);
    cudaGetSymbolAddress(&aggp, g_aggh);
    float* gx = (float*)xp;
    __half2* gxh = (__half2*)xhp;
    __half2* agg0 = (__half2*)aggp;
    __half2* agg1 = agg0 + (size_t)NN * 64;

    const int GRID_KAN = (NN + MT - 1) / MT;   // 391

    // launches: 1 setup  2 deg  3 scatter0  4 kan0 (ncu capture)  5 scatter1  6 kan1
    setup_kernel<<<(int)((N_SETUP + 255) / 256), 256>>>(x, bwl, swl, bwc, swc, (const int*)ei);
    deg_kernel<<<(EE + 255) / 256, 256>>>(ei);

    scatter_half<<<(int)((EE * 16LL + 255) / 256), 256>>>((const uint4*)gxh, ei, agg0);
    kan_fused<1><<<GRID_KAN, NTHR, KAN_SMEM>>>(gxh, agg0, x, gx, gxh);

    scatter_half<<<(int)((EE * 16LL + 255) / 256), 256>>>((const uint4*)gxh, ei, agg1);
    kan_fused<0><<<GRID_KAN, NTHR, KAN_SMEM>>>(gxh, agg1, gx, out, gxh);
}